// round 16
// baseline (speedup 1.0000x reference)
#include <cuda_runtime.h>
#include <cuda_fp16.h>

#define NLAT_IN  181
#define NLON_IN  360
#define NLAT_OUT 361
#define NLON_OUT 720
#define KSIZE    3
#define CIN      16
#define COUT     16
#define NNZ      8192
#define NBIN     (NLAT_OUT * 2)   // (hi, parity)
#define MAXB     128
#define NEIN     (NLAT_IN * KSIZE)  // 543 einsum blocks
#define NBINB    64                 // binning blocks (128 entries each)
#define NROW     (KSIZE * NLAT_IN)  // 543 xw rows

// xw: [row][h][w] as uint4 (8 fp16 channels packed). 6.25MB
__device__ uint4 d_xw4[NROW * 2 * NLON_IN];
// Two independent bucket copies (one per channel-half k_main block).
// Entry: {meta, val_bits, orig_idx, 0}; meta = (row4<<9)|s
__device__ int4 d_bk0[NBIN * MAXB];
__device__ int4 d_bk1[NBIN * MAXB];
__device__ int  d_cnt0[NBIN];   // statically zero; each k_main block resets its own
__device__ int  d_cnt1[NBIN];

// ---------------------------------------------------------------------------
// Fused: blocks 0..542 = channel-mix einsum; blocks 543..606 = atomic binning.
__global__ void __launch_bounds__(768)
k_prep(const float* __restrict__ x, const float* __restrict__ wgt,
       const int* __restrict__ ker_idx, const int* __restrict__ row_idx,
       const int* __restrict__ col_idx, const float* __restrict__ vals) {
    int t = threadIdx.x;

    if (blockIdx.x >= NEIN) {
        // ---------------- binning path ----------------
        if (t >= 128) return;
        int i   = (blockIdx.x - NEIN) * 128 + t;
        int col = col_idx[i];
        int hi  = col / NLON_OUT;
        int p   = col - hi * NLON_OUT;
        int bin = hi * 2 + (p & 1);
        int row4 = (ker_idx[i] * NLAT_IN + row_idx[i]) * (2 * NLON_IN);
        int4 ent = make_int4((row4 << 9) | (p >> 1),
                             __float_as_int(vals[i]), i, 0);
        int s0 = atomicAdd(&d_cnt0[bin], 1);
        if (s0 < MAXB) d_bk0[bin * MAXB + s0] = ent;
        int s1 = atomicAdd(&d_cnt1[bin], 1);
        if (s1 < MAXB) d_bk1[bin * MAXB + s1] = ent;
        return;
    }

    // ---------------- einsum path ----------------
    // block b: tin = b % 181, k = b / 181. h=0: ch 0..7, h=1: ch 8..15.
    __shared__ float sw[COUT * CIN];  // [o][c] for this k
    int b   = blockIdx.x;
    int tin = b % NLAT_IN;
    int k   = b / NLAT_IN;
    if (t < COUT * CIN) sw[t] = wgt[t * KSIZE + k];  // wgt[o][c][k]
    __syncthreads();

    int h = (t >= 384) ? 1 : 0;
    int w = t - h * 384;
    if (w >= NLON_IN) return;

    float acc[8];
#pragma unroll
    for (int o = 0; o < 8; o++) acc[o] = 0.f;

#pragma unroll
    for (int c = 0; c < CIN; c++) {
        float xc = x[(c * NLAT_IN + tin) * NLON_IN + w];
#pragma unroll
        for (int o = 0; o < 8; o++)
            acc[o] += xc * sw[(h * 8 + o) * CIN + c];
    }
    __half2 p0 = __floats2half2_rn(acc[0], acc[1]);
    __half2 p1 = __floats2half2_rn(acc[2], acc[3]);
    __half2 p2 = __floats2half2_rn(acc[4], acc[5]);
    __half2 p3 = __floats2half2_rn(acc[6], acc[7]);
    uint4 val;
    val.x = *(unsigned*)&p0;
    val.y = *(unsigned*)&p1;
    val.z = *(unsigned*)&p2;
    val.w = *(unsigned*)&p3;
    d_xw4[(k * NLAT_IN + tin) * (2 * NLON_IN) + h * NLON_IN + w] = val;
}

// ---------------------------------------------------------------------------
// main gather (R11 body + PDL entry): one block per (bin, channel-half).
// Stages its private bucket, rank-sorts by original index (determinism),
// resets its own counter, then 1 x LDG.128 per entry, 4 in flight,
// sentinel-padded (no tail loop).
__global__ void __launch_bounds__(384)
k_main(const float* __restrict__ bias, float* __restrict__ out) {
#if __CUDA_ARCH__ >= 900
    cudaGridDependencySynchronize();
#endif
    __shared__ int  sidx[MAXB];
    __shared__ int2 sraw[MAXB];
    __shared__ __align__(16) int2 se[MAXB];
    int bb = blockIdx.x;
    int b  = bb >> 1;          // bin
    int h  = bb & 1;           // channel half
    int hi = b >> 1;
    int q  = b & 1;
    int tid = threadIdx.x;

    int* cntp = h ? d_cnt1 : d_cnt0;
    const int4* bk = (h ? d_bk1 : d_bk0) + b * MAXB;

    int cnt = cntp[b];
    if (cnt > MAXB) cnt = MAXB;
    int cntP = (cnt + 3) & ~3;
    if (tid < cnt) {
        int4 e = bk[tid];
        sraw[tid] = make_int2(e.x, e.y);
        sidx[tid] = e.z;
    }
    __syncthreads();
    if (tid == 0) cntp[b] = 0;          // reset for next graph replay
    if (tid < cnt) {
        int my = sidx[tid];
        int r = 0;
        for (int j = 0; j < cnt; j++) r += (sidx[j] < my);
        se[r] = sraw[tid];
    }
    if (tid >= cnt && tid < cntP) se[tid] = make_int2(0, 0);  // sentinel
    __syncthreads();

    int jj = tid;
    if (jj >= NLON_IN) return;

    const uint4* __restrict__ xbase = d_xw4 + h * NLON_IN;
    float acc[8];
#pragma unroll
    for (int o = 0; o < 8; o++) acc[o] = 0.f;

    const int4* se4 = (const int4*)se;
    for (int e = 0; e < cntP; e += 4) {
        int4 A = se4[e >> 1];
        int4 B = se4[(e >> 1) + 1];
        int m0 = A.x, m1 = A.z, m2 = B.x, m3 = B.z;
        float v0 = __int_as_float(A.y), v1 = __int_as_float(A.w);
        float v2 = __int_as_float(B.y), v3 = __int_as_float(B.w);
        int w0 = jj - (m0 & 511); if (w0 < 0) w0 += NLON_IN;
        int w1 = jj - (m1 & 511); if (w1 < 0) w1 += NLON_IN;
        int w2 = jj - (m2 & 511); if (w2 < 0) w2 += NLON_IN;
        int w3 = jj - (m3 & 511); if (w3 < 0) w3 += NLON_IN;
        uint4 d0 = xbase[(m0 >> 9) + w0];
        uint4 d1 = xbase[(m1 >> 9) + w1];
        uint4 d2 = xbase[(m2 >> 9) + w2];
        uint4 d3 = xbase[(m3 >> 9) + w3];
#pragma unroll
        for (int j = 0; j < 4; j++) {
            float2 f0 = __half22float2(*(const __half2*)(&d0.x + j));
            float2 f1 = __half22float2(*(const __half2*)(&d1.x + j));
            float2 f2 = __half22float2(*(const __half2*)(&d2.x + j));
            float2 f3 = __half22float2(*(const __half2*)(&d3.x + j));
            acc[2 * j]     += v0 * f0.x + v1 * f1.x + v2 * f2.x + v3 * f3.x;
            acc[2 * j + 1] += v0 * f0.y + v1 * f1.y + v2 * f2.y + v3 * f3.y;
        }
    }

    int lon = q + 2 * jj;
    const int cs = NLAT_OUT * NLON_OUT;
    float* dst = out + (h * 8) * cs + hi * NLON_OUT + lon;
#pragma unroll
    for (int o = 0; o < 8; o++) dst[o * cs] = acc[o] + bias[h * 8 + o];
}

// ---------------------------------------------------------------------------
extern "C" void kernel_launch(void* const* d_in, const int* in_sizes, int n_in,
                              void* d_out, int out_size) {
    const float* x       = (const float*)d_in[0];
    const float* weight  = (const float*)d_in[1];
    const float* bias    = (const float*)d_in[2];
    const int*   ker_idx = (const int*)d_in[3];
    const int*   row_idx = (const int*)d_in[4];
    const int*   col_idx = (const int*)d_in[5];
    const float* vals    = (const float*)d_in[6];
    float* out = (float*)d_out;

    (void)in_sizes; (void)n_in; (void)out_size;

    k_prep<<<NEIN + NBINB, 768>>>(x, weight, ker_idx, row_idx, col_idx, vals);

    cudaLaunchConfig_t cfg = {};
    cfg.gridDim  = dim3(NBIN * 2, 1, 1);
    cfg.blockDim = dim3(384, 1, 1);
    cudaLaunchAttribute attr[1];
    attr[0].id = cudaLaunchAttributeProgrammaticStreamSerialization;
    attr[0].val.programmaticStreamSerializationAllowed = 1;
    cfg.attrs = attr;
    cfg.numAttrs = 1;
    cudaLaunchKernelEx(&cfg, k_main, bias, out);
}

// round 17
// speedup vs baseline: 1.1131x; 1.1131x over previous
#include <cuda_runtime.h>
#include <cuda_fp16.h>

#define NLAT_IN  181
#define NLON_IN  360
#define NLAT_OUT 361
#define NLON_OUT 720
#define KSIZE    3
#define CIN      16
#define COUT     16
#define NNZ      8192
#define NBIN     (NLAT_OUT * 2)   // (hi, parity)
#define MAXB     128
#define NEIN     (NLAT_IN * KSIZE)  // 543 einsum blocks
#define NBINB    64                 // binning blocks (128 entries each)
#define NROW     (KSIZE * NLAT_IN)  // 543 xw rows

// xw: [row][h][w] as uint4 (8 fp16 channels packed). 6.25MB
__device__ uint4 d_xw4[NROW * 2 * NLON_IN];
// Two independent bucket copies (one per channel-half k_main block).
// Entry: {meta, val_bits, orig_idx, 0}; meta = (row4<<9)|s
__device__ int4 d_bk0[NBIN * MAXB];
__device__ int4 d_bk1[NBIN * MAXB];
__device__ int  d_cnt0[NBIN];   // statically zero; each k_main block resets its own
__device__ int  d_cnt1[NBIN];

// ---------------------------------------------------------------------------
// Fused: blocks 0..542 = channel-mix einsum; blocks 543..606 = atomic binning.
__global__ void __launch_bounds__(768)
k_prep(const float* __restrict__ x, const float* __restrict__ wgt,
       const int* __restrict__ ker_idx, const int* __restrict__ row_idx,
       const int* __restrict__ col_idx, const float* __restrict__ vals) {
    int t = threadIdx.x;

    if (blockIdx.x >= NEIN) {
        // ---------------- binning path ----------------
        if (t >= 128) return;
        int i   = (blockIdx.x - NEIN) * 128 + t;
        int col = col_idx[i];
        int hi  = col / NLON_OUT;
        int p   = col - hi * NLON_OUT;
        int bin = hi * 2 + (p & 1);
        int row4 = (ker_idx[i] * NLAT_IN + row_idx[i]) * (2 * NLON_IN);
        int4 ent = make_int4((row4 << 9) | (p >> 1),
                             __float_as_int(vals[i]), i, 0);
        int s0 = atomicAdd(&d_cnt0[bin], 1);
        if (s0 < MAXB) d_bk0[bin * MAXB + s0] = ent;
        int s1 = atomicAdd(&d_cnt1[bin], 1);
        if (s1 < MAXB) d_bk1[bin * MAXB + s1] = ent;
        return;
    }

    // ---------------- einsum path ----------------
    // block b: tin = b % 181, k = b / 181. h=0: ch 0..7, h=1: ch 8..15.
    __shared__ float sw[COUT * CIN];  // [o][c] for this k
    int b   = blockIdx.x;
    int tin = b % NLAT_IN;
    int k   = b / NLAT_IN;
    if (t < COUT * CIN) sw[t] = wgt[t * KSIZE + k];  // wgt[o][c][k]
    __syncthreads();

    int h = (t >= 384) ? 1 : 0;
    int w = t - h * 384;
    if (w >= NLON_IN) return;

    float acc[8];
#pragma unroll
    for (int o = 0; o < 8; o++) acc[o] = 0.f;

#pragma unroll
    for (int c = 0; c < CIN; c++) {
        float xc = x[(c * NLAT_IN + tin) * NLON_IN + w];
#pragma unroll
        for (int o = 0; o < 8; o++)
            acc[o] += xc * sw[(h * 8 + o) * CIN + c];
    }
    __half2 p0 = __floats2half2_rn(acc[0], acc[1]);
    __half2 p1 = __floats2half2_rn(acc[2], acc[3]);
    __half2 p2 = __floats2half2_rn(acc[4], acc[5]);
    __half2 p3 = __floats2half2_rn(acc[6], acc[7]);
    uint4 val;
    val.x = *(unsigned*)&p0;
    val.y = *(unsigned*)&p1;
    val.z = *(unsigned*)&p2;
    val.w = *(unsigned*)&p3;
    d_xw4[(k * NLAT_IN + tin) * (2 * NLON_IN) + h * NLON_IN + w] = val;
}

// ---------------------------------------------------------------------------
// main gather: one block per (bin, channel-half); 192 threads. Thread jj
// handles lons q+2*jj and q+2*(jj+180). Group-of-4 entries accumulated in
// __half2 (HMUL2/HFMA2), flushed to fp32 once per group. v pre-packed to
// broadcast half2 at staging. Sentinel padding (v=0) -> no tail loop.
__global__ void __launch_bounds__(192, 5)
k_main(const float* __restrict__ bias, float* __restrict__ out) {
    __shared__ int  sidx[MAXB];
    __shared__ int2 sraw[MAXB];
    __shared__ __align__(16) int2 se[MAXB];   // sorted {meta, v_half2x2}
    int bb = blockIdx.x;
    int b  = bb >> 1;          // bin
    int h  = bb & 1;           // channel half
    int hi = b >> 1;
    int q  = b & 1;
    int tid = threadIdx.x;

    int* cntp = h ? d_cnt1 : d_cnt0;
    const int4* bk = (h ? d_bk1 : d_bk0) + b * MAXB;

    int cnt = cntp[b];
    if (cnt > MAXB) cnt = MAXB;
    int cntP = (cnt + 3) & ~3;
    if (tid < cnt) {
        int4 e = bk[tid];
        __half2 v2 = __half2half2(__float2half(__int_as_float(e.y)));
        sraw[tid] = make_int2(e.x, *(int*)&v2);
        sidx[tid] = e.z;
    }
    __syncthreads();
    if (tid == 0) cntp[b] = 0;          // reset for next graph replay
    if (tid < cnt) {
        int my = sidx[tid];
        int r = 0;
        for (int j = 0; j < cnt; j++) r += (sidx[j] < my);
        se[r] = sraw[tid];
    }
    if (tid >= cnt && tid < cntP) se[tid] = make_int2(0, 0);  // sentinel
    __syncthreads();

    int jj = tid;
    if (jj >= 180) return;

    const uint4* __restrict__ xbase = d_xw4 + h * NLON_IN;
    float acc[16];                    // [lon-half][8 ch]
#pragma unroll
    for (int o = 0; o < 16; o++) acc[o] = 0.f;

    const int4* se4 = (const int4*)se;
    for (int e = 0; e < cntP; e += 4) {
        int4 A = se4[e >> 1];
        int4 B = se4[(e >> 1) + 1];
        int m0 = A.x, m1 = A.z, m2 = B.x, m3 = B.z;
        __half2 v0 = *(__half2*)&A.y, v1 = *(__half2*)&A.w;
        __half2 v2 = *(__half2*)&B.y, v3 = *(__half2*)&B.w;
        int wa0 = jj - (m0 & 511); if (wa0 < 0) wa0 += NLON_IN;
        int wa1 = jj - (m1 & 511); if (wa1 < 0) wa1 += NLON_IN;
        int wa2 = jj - (m2 & 511); if (wa2 < 0) wa2 += NLON_IN;
        int wa3 = jj - (m3 & 511); if (wa3 < 0) wa3 += NLON_IN;
        int wb0 = wa0 + 180; if (wb0 >= NLON_IN) wb0 -= NLON_IN;
        int wb1 = wa1 + 180; if (wb1 >= NLON_IN) wb1 -= NLON_IN;
        int wb2 = wa2 + 180; if (wb2 >= NLON_IN) wb2 -= NLON_IN;
        int wb3 = wa3 + 180; if (wb3 >= NLON_IN) wb3 -= NLON_IN;
        uint4 da0 = xbase[(m0 >> 9) + wa0];
        uint4 db0 = xbase[(m0 >> 9) + wb0];
        uint4 da1 = xbase[(m1 >> 9) + wa1];
        uint4 db1 = xbase[(m1 >> 9) + wb1];
        uint4 da2 = xbase[(m2 >> 9) + wa2];
        uint4 db2 = xbase[(m2 >> 9) + wb2];
        uint4 da3 = xbase[(m3 >> 9) + wa3];
        uint4 db3 = xbase[(m3 >> 9) + wb3];
#pragma unroll
        for (int j = 0; j < 4; j++) {
            __half2 sA = __hmul2(*(const __half2*)(&da3.x + j), v3);
            sA = __hfma2(*(const __half2*)(&da2.x + j), v2, sA);
            sA = __hfma2(*(const __half2*)(&da1.x + j), v1, sA);
            sA = __hfma2(*(const __half2*)(&da0.x + j), v0, sA);
            float2 fA = __half22float2(sA);
            acc[2 * j]     += fA.x;
            acc[2 * j + 1] += fA.y;
            __half2 sB = __hmul2(*(const __half2*)(&db3.x + j), v3);
            sB = __hfma2(*(const __half2*)(&db2.x + j), v2, sB);
            sB = __hfma2(*(const __half2*)(&db1.x + j), v1, sB);
            sB = __hfma2(*(const __half2*)(&db0.x + j), v0, sB);
            float2 fB = __half22float2(sB);
            acc[8 + 2 * j]     += fB.x;
            acc[8 + 2 * j + 1] += fB.y;
        }
    }

    int lon0 = q + 2 * jj;
    const int cs = NLAT_OUT * NLON_OUT;
    float* dst0 = out + hi * NLON_OUT + lon0;
    float* dst1 = dst0 + 360;
    const float* bp = bias + h * 8;
    float* dsth = dst0 + (h * 8) * cs;
    float* dsth1 = dst1 + (h * 8) * cs;
#pragma unroll
    for (int o = 0; o < 8; o++) {
        float bv = bp[o];
        dsth[o * cs]  = acc[o] + bv;
        dsth1[o * cs] = acc[8 + o] + bv;
    }
}

// ---------------------------------------------------------------------------
extern "C" void kernel_launch(void* const* d_in, const int* in_sizes, int n_in,
                              void* d_out, int out_size) {
    const float* x       = (const float*)d_in[0];
    const float* weight  = (const float*)d_in[1];
    const float* bias    = (const float*)d_in[2];
    const int*   ker_idx = (const int*)d_in[3];
    const int*   row_idx = (const int*)d_in[4];
    const int*   col_idx = (const int*)d_in[5];
    const float* vals    = (const float*)d_in[6];
    float* out = (float*)d_out;

    (void)in_sizes; (void)n_in; (void)out_size;

    k_prep<<<NEIN + NBINB, 768>>>(x, weight, ker_idx, row_idx, col_idx, vals);
    k_main<<<NBIN * 2, 192>>>(bias, out);
}